// round 17
// baseline (speedup 1.0000x reference)
#include <cuda_runtime.h>

// Problem constants (fixed shapes from reference)
#define Bn  4
#define Cn  128
#define Hn  64
#define Wn  64
#define Ln  16
#define Kn  64
#define CDn 8
#define HW  (Hn * Wn)

typedef unsigned long long u64;

// ---- packed f32x2 helpers ----
__device__ __forceinline__ u64 pack2(float x, float y) {
    u64 r; asm("mov.b64 %0, {%1, %2};" : "=l"(r) : "f"(x), "f"(y)); return r;
}
__device__ __forceinline__ void unpack2(u64 v, float& x, float& y) {
    asm("mov.b64 {%0, %1}, %2;" : "=f"(x), "=f"(y) : "l"(v));
}
__device__ __forceinline__ u64 add2(u64 a, u64 b) {
    u64 d; asm("add.rn.f32x2 %0, %1, %2;" : "=l"(d) : "l"(a), "l"(b)); return d;
}
__device__ __forceinline__ u64 fma2(u64 a, u64 b, u64 c) {
    u64 d; asm("fma.rn.f32x2 %0, %1, %2, %3;" : "=l"(d) : "l"(a), "l"(b), "l"(c)); return d;
}
__device__ __forceinline__ u64 mul2(u64 a, u64 b) {
    u64 d; asm("mul.rn.f32x2 %0, %1, %2;" : "=l"(d) : "l"(a), "l"(b), "l"(b)); return d;
}

// PIXEL-QUAD lane packing:
//   One thread: one (b, l, w) at FOUR pixels h0..h0+3. Two f32x2 chains per
//   code — chain q holds pixels (h0+2q, h0+2q+1) in its two lanes. Codes are
//   pre-duplicated {-c_j, -c_j} in smem, so:
//     * 4 LDS.128 per code serve 4 evals (1 LDS/eval, same as R16)
//     * 4 wide ops per eval (HALF of R16's 8) and ZERO cross-lane FADDs
//   Each lane accumulates a complete sequential 8-dim diff-form sum ->
//   exact math, deterministic. Tracking: FMNMX best + off-chain SEL index
//   (strict <, first-k-wins == reference argmin). No guard needed.
__global__ __launch_bounds__(64) void vq_kernel(
    const float* __restrict__ z,      // (B, C, H, W)
    const float* __restrict__ codes,  // (L, K, CD)
    float* __restrict__ qout,         // (B, C, H, W) or null
    float* __restrict__ idxf,         // (B, H, W, L) as float or null
    int*   __restrict__ idxi)         // (B, H, W, L) as int or null
{
    // Duplicated negated codes for this block's l:
    //   cd[k*8 + j] = {-c_j, -c_j}
    __shared__ __align__(16) u64 cd[Kn * CDn];   // 4 KB

    const int tid = threadIdx.x;   // 64 threads
    const int l   = blockIdx.x;

    // Pre-pack: thread t owns code t.
    {
        const float4 va = reinterpret_cast<const float4*>(
            codes + (l * Kn + tid) * CDn)[0];
        const float4 vb = reinterpret_cast<const float4*>(
            codes + (l * Kn + tid) * CDn)[1];
        ulonglong2* e = reinterpret_cast<ulonglong2*>(cd + tid * CDn);
        e[0] = make_ulonglong2(pack2(-va.x, -va.x), pack2(-va.y, -va.y));
        e[1] = make_ulonglong2(pack2(-va.z, -va.z), pack2(-va.w, -va.w));
        e[2] = make_ulonglong2(pack2(-vb.x, -vb.x), pack2(-vb.y, -vb.y));
        e[3] = make_ulonglong2(pack2(-vb.z, -vb.z), pack2(-vb.w, -vb.w));
    }
    __syncthreads();

    const int w  = tid;
    const int h0 = blockIdx.y * 4;
    const int b  = blockIdx.z;

    // z for 4 pixels x 8 dims, packed per dim across pixel pairs:
    //   zz[q][j] = {z_j(h0+2q), z_j(h0+2q+1)}
    u64 zz[2][8];
    {
        const float* zb = z + ((b * Cn + l * CDn) * Hn + h0) * Wn + w;
        #pragma unroll
        for (int j = 0; j < 8; j++) {
            const float* pj = zb + j * HW;
            zz[0][j] = pack2(pj[0],      pj[Wn]);
            zz[1][j] = pack2(pj[2 * Wn], pj[3 * Wn]);
        }
    }

    const ulonglong2* __restrict__ cb =
        reinterpret_cast<const ulonglong2*>(cd);

    float best[4] = {3.4e38f, 3.4e38f, 3.4e38f, 3.4e38f};
    int   bi[4]   = {0, 0, 0, 0};

    #pragma unroll
    for (int k = 0; k < Kn; k++) {
        const ulonglong2 q0 = cb[4 * k + 0];   // dims 0,1 (dup)
        const ulonglong2 q1 = cb[4 * k + 1];   // dims 2,3
        const ulonglong2 q2 = cb[4 * k + 2];   // dims 4,5
        const ulonglong2 q3 = cb[4 * k + 3];   // dims 6,7
        #pragma unroll
        for (int q = 0; q < 2; q++) {          // pixel pair
            u64 t, d;
            t = add2(zz[q][0], q0.x); d = mul2(t, t);
            t = add2(zz[q][1], q0.y); d = fma2(t, t, d);
            t = add2(zz[q][2], q1.x); d = fma2(t, t, d);
            t = add2(zz[q][3], q1.y); d = fma2(t, t, d);
            t = add2(zz[q][4], q2.x); d = fma2(t, t, d);
            t = add2(zz[q][5], q2.y); d = fma2(t, t, d);
            t = add2(zz[q][6], q3.x); d = fma2(t, t, d);
            t = add2(zz[q][7], q3.y); d = fma2(t, t, d);
            float d0, d1; unpack2(d, d0, d1);  // register aliasing
            // exact tracking, strict <, first-k-wins
            const float o0 = best[2 * q];
            best[2 * q]     = fminf(o0, d0);
            bi[2 * q]       = (d0 < o0) ? k : bi[2 * q];
            const float o1 = best[2 * q + 1];
            best[2 * q + 1] = fminf(o1, d1);
            bi[2 * q + 1]   = (d1 < o1) ? k : bi[2 * q + 1];
        }
    }

    // ---- Outputs (negated code = lo lane of the duplicated u64) ----
    const float* __restrict__ cneg = reinterpret_cast<const float*>(cd);
    #pragma unroll
    for (int p = 0; p < 4; p++) {
        const int kb = bi[p];
        const int h  = h0 + p;
        if (qout) {
            float* qb = qout + ((b * Cn + l * CDn) * Hn + h) * Wn + w;
            #pragma unroll
            for (int j = 0; j < 8; j++)
                qb[j * HW] = -cneg[(kb * CDn + j) * 2];
        }
        const long long io = (((long long)b * Hn + h) * Wn + w) * Ln + l;
        if (idxf) idxf[io] = (float)kb;
        if (idxi) idxi[io] = kb;
    }
}

extern "C" void kernel_launch(void* const* d_in, const int* in_sizes, int n_in,
                              void* d_out, int out_size)
{
    const float* z     = (const float*)d_in[0];
    const float* codes = (const float*)d_in[1];
    // Defensive: if input order is (codes, z), swap by element count.
    if (n_in >= 2 && in_sizes[0] == Ln * Kn * CDn && in_sizes[1] == Bn * Cn * HW) {
        codes = (const float*)d_in[0];
        z     = (const float*)d_in[1];
    }

    const int NQ = Bn * Cn * HW;       // 2097152
    const int NI = Bn * HW * Ln;       // 262144

    float* qout = nullptr;
    float* idxf = nullptr;
    int*   idxi = nullptr;

    if (out_size >= NQ + NI) {           // both outputs, flattened, float dtype
        qout = (float*)d_out;
        idxf = (float*)d_out + NQ;
    } else if (out_size == NI) {         // idx only -> int dtype
        idxi = (int*)d_out;
    } else {                             // quantized only
        qout = (float*)d_out;
    }

    dim3 grid(Ln, Hn / 4, Bn);       // (16, 16, 4) = 1024 blocks
    dim3 block(64, 1, 1);            // 64 threads (2 warps)
    vq_kernel<<<grid, block>>>(z, codes, qout, idxf, idxi);
}